// round 6
// baseline (speedup 1.0000x reference)
#include <cuda_runtime.h>
#include <cstdint>

// ---------------- scratch (no mallocs allowed) ----------------
__device__ float g_S[16 * 4 * 18 * 4096];       // conv tap partials, 18.9 MB
__device__ float g_offset[4 * 2 * 4096];        // [b][oc][pix]
// B in mma-fragment order: [b][nt32][k8:128][n8:16][lane:32][2]  (67 MB)
__device__ float g_Bfrag[4ULL * 32 * 128 * 1024];
// A in mma-fragment order: [mt16][k8:128][m16:8][lane:32][4]     (8 MB)
__device__ float g_Afrag[16ULL * 128 * 1024];

__device__ __forceinline__ uint32_t f2tf(float x) {
    uint32_t r;
    asm("cvt.rna.tf32.f32 %0, %1;" : "=r"(r) : "f"(x));
    return r;
}

#define FMA2(d, a, b, c) \
    asm("fma.rn.f32x2 %0, %1, %2, %3;" : "=l"(d) : "l"(a), "l"(b), "l"(c))

// =====================================================================
// Kernel 1a: tap-decomposed offset conv, stage 1 (channel reduction).
// =====================================================================
__global__ __launch_bounds__(256) void conv_taps_kernel(
    const float* __restrict__ refer, const float* __restrict__ sup,
    const float* __restrict__ w_off)
{
    __shared__ float2 wsh[128 * 18];

    int split = blockIdx.z;
    int b     = blockIdx.y;
    int c0    = split * 128;
    int tid   = threadIdx.x;

    for (int i = tid; i < 128 * 18; i += 256) {
        int c = i / 18, tap = i - c * 18;
        int oc = tap / 9, t9 = tap - oc * 9;
        float w = w_off[((size_t)oc * 2048 + c0 + c) * 9 + t9];
        wsh[i] = make_float2(w, w);
    }
    __syncthreads();

    const float* src = (c0 < 1024)
        ? refer + ((size_t)b * 1024 + c0) * 4096
        : sup   + ((size_t)b * 1024 + (c0 - 1024)) * 4096;

    int px = (blockIdx.x * 256 + tid) * 2;

    unsigned long long acc[18];
    #pragma unroll
    for (int t = 0; t < 18; ++t) acc[t] = 0ull;

    #pragma unroll 2
    for (int c = 0; c < 128; ++c) {
        unsigned long long v =
            *(const unsigned long long*)(src + (size_t)c * 4096 + px);
        const unsigned long long* wp = (const unsigned long long*)&wsh[c * 18];
        #pragma unroll
        for (int t = 0; t < 18; ++t) FMA2(acc[t], wp[t], v, acc[t]);
    }

    float* outb = g_S + (((size_t)split * 4 + b) * 18) * 4096 + px;
    #pragma unroll
    for (int t = 0; t < 18; ++t)
        *(unsigned long long*)(outb + (size_t)t * 4096) = acc[t];
}

// =====================================================================
// Kernel 1b: combine shifted taps + reduce splits -> offsets.
// =====================================================================
__global__ __launch_bounds__(256) void offset_combine_kernel(
    const float* __restrict__ b_off)
{
    int pix = blockIdx.x * 256 + threadIdx.x;
    int b   = blockIdx.y;
    int y = pix >> 6, x = pix & 63;

    #pragma unroll
    for (int oc = 0; oc < 2; ++oc) {
        float acc = b_off[oc];
        #pragma unroll
        for (int ky = 0; ky < 3; ++ky) {
            int yy = y + ky - 1;
            bool vy = (yy >= 0) && (yy < 64);
            #pragma unroll
            for (int kx = 0; kx < 3; ++kx) {
                int xx = x + kx - 1;
                if (vy && xx >= 0 && xx < 64) {
                    int sp = yy * 64 + xx;
                    int tap = oc * 9 + ky * 3 + kx;
                    #pragma unroll 4
                    for (int s = 0; s < 16; ++s)
                        acc += g_S[(((size_t)s * 4 + b) * 18 + tap) * 4096 + sp];
                }
            }
        }
        g_offset[(b * 2 + oc) * 4096 + pix] = acc;
    }
}

// =====================================================================
// Kernel 2: bilinear gather-sample -> B in mma-fragment order, tf32.
// =====================================================================
__global__ __launch_bounds__(256) void sample_kernel(
    const float* __restrict__ sup)
{
    int pix = blockIdx.x * 256 + threadIdx.x;
    int b   = blockIdx.y;
    int cq  = blockIdx.z;

    float o0 = g_offset[(b * 2 + 0) * 4096 + pix];
    float o1 = g_offset[(b * 2 + 1) * 4096 + pix];

    int h = pix >> 6, w = pix & 63;
    float py = o0 + (float)h;
    float px = o1 + (float)w;
    float y0f = floorf(py), x0f = floorf(px);
    float wy = py - y0f, wx = px - x0f;
    int y0 = (int)y0f, x0 = (int)x0f;
    int y1 = y0 + 1,  x1 = x0 + 1;

    float vy0 = (y0 >= 0 && y0 < 64) ? 1.f : 0.f;
    float vy1 = (y1 >= 0 && y1 < 64) ? 1.f : 0.f;
    float vx0 = (x0 >= 0 && x0 < 64) ? 1.f : 0.f;
    float vx1 = (x1 >= 0 && x1 < 64) ? 1.f : 0.f;
    int cy0 = min(max(y0, 0), 63), cy1 = min(max(y1, 0), 63);
    int cx0 = min(max(x0, 0), 63), cx1 = min(max(x1, 0), 63);
    int i00 = cy0 * 64 + cx0, i01 = cy0 * 64 + cx1;
    int i10 = cy1 * 64 + cx0, i11 = cy1 * 64 + cx1;
    float w00 = (1.f - wy) * (1.f - wx) * vy0 * vx0;
    float w01 = (1.f - wy) * wx         * vy0 * vx1;
    float w10 = wy * (1.f - wx)         * vy1 * vx0;
    float w11 = wy * wx                 * vy1 * vx1;

    const float* base = sup + ((size_t)b * 1024 + cq * 256) * 4096;

    int nt = pix >> 7, n8 = (pix >> 3) & 15, g = pix & 7;
    float* outb = g_Bfrag + (((size_t)b * 32 + nt) * 128) * 1024;

    for (int k8 = 0; k8 < 32; ++k8) {
        int k8g = cq * 32 + k8;
        float buf[8];
        #pragma unroll
        for (int j = 0; j < 8; ++j) {
            const float* p = base + (size_t)(k8 * 8 + j) * 4096;
            float r = w00 * p[i00] + w01 * p[i01] + w10 * p[i10] + w11 * p[i11];
            buf[(j & 3) * 2 + (j >> 2)] = __uint_as_float(f2tf(r));
        }
        float* dst = outb + (size_t)k8g * 1024 + n8 * 64 + g * 8;
        *(float4*)dst       = *(float4*)buf;
        *(float4*)(dst + 4) = *(float4*)(buf + 4);
    }
}

// =====================================================================
// Kernel 2b: w_def -> tf32, mma A-fragment order.
// =====================================================================
__global__ __launch_bounds__(256) void wdef_frag_kernel(
    const float* __restrict__ wd)
{
    int t = blockIdx.x * 256 + threadIdx.x;   // (o, k8)
    int o = t >> 7, k8 = t & 127;
    int mt = o >> 7, mrow = o & 127;
    int m16 = mrow >> 4, r16 = mrow & 15;
    int g = r16 & 7, hi = r16 >> 3;

    const float* src = wd + (size_t)o * 1024 + k8 * 8;
    float* dstc = g_Afrag + ((size_t)mt * 128 + k8) * 1024 + m16 * 128;

    #pragma unroll
    for (int j = 0; j < 8; ++j) {
        int tg = j & 3, chi = j >> 2;
        dstc[(g * 4 + tg) * 4 + hi + 2 * chi] =
            __uint_as_float(f2tf(src[j]));
    }
}

// =====================================================================
// Kernel 3: tf32 mma.sync GEMM, CTA tile 128(M) x 256(N), warp 64x64.
// 8 warps (2x4). 4-stage cp.async pipeline, 24KB/stage
// (A 8KB + B 16KB per k16). Pure vector LDS + mma in the loop.
// =====================================================================
__device__ __forceinline__ void mma_tf32(float* c, const uint32_t* a, const uint32_t* bb) {
    asm volatile(
        "mma.sync.aligned.m16n8k8.row.col.f32.tf32.tf32.f32 "
        "{%0,%1,%2,%3},{%4,%5,%6,%7},{%8,%9},{%0,%1,%2,%3};"
        : "+f"(c[0]), "+f"(c[1]), "+f"(c[2]), "+f"(c[3])
        : "r"(a[0]), "r"(a[1]), "r"(a[2]), "r"(a[3]), "r"(bb[0]), "r"(bb[1]));
}

__device__ __forceinline__ void cpa16(float* smem, const float* g) {
    uint32_t s = (uint32_t)__cvta_generic_to_shared(smem);
    asm volatile("cp.async.cg.shared.global [%0], [%1], 16;\n" :: "r"(s), "l"(g) : "memory");
}

static constexpr int STAGE_FLOATS = 6144;                // A 2048 + B 4096
static constexpr int GEMM_SMEM = 4 * STAGE_FLOATS * 4;   // 96 KB

__global__ __launch_bounds__(256, 1) void gemm_kernel(float* __restrict__ Out)
{
    extern __shared__ float sm[];

    int tid = threadIdx.x;
    int warp = tid >> 5, lane = tid & 31;
    int wm = warp >> 2, wn = warp & 3;
    int nt2 = blockIdx.x, mt = blockIdx.y, b = blockIdx.z;

    const float* Ag  = g_Afrag + (size_t)mt * 128 * 1024;
    const float* Bg0 = g_Bfrag + ((size_t)b * 32 + nt2 * 2) * 128 * 1024;
    const float* Bg1 = Bg0 + (size_t)128 * 1024;

    // stage layout (floats): A [kk:2][1024], B [kk:2][nh:2][1024]
#define LOAD(s, kt) do {                                                   \
    float* dA = sm + (s) * STAGE_FLOATS;                                   \
    float* dB = dA + 2048;                                                 \
    const float* ga  = Ag  + (size_t)(kt) * 2048;                          \
    const float* gb0 = Bg0 + (size_t)(kt) * 2048;                          \
    const float* gb1 = Bg1 + (size_t)(kt) * 2048;                          \
    cpa16(dA + tid * 4,          ga  + tid * 4);                           \
    cpa16(dA + 1024 + tid * 4,   ga  + 1024 + tid * 4);                    \
    cpa16(dB + tid * 4,          gb0 + tid * 4);                           \
    cpa16(dB + 2048 + tid * 4,   gb0 + 1024 + tid * 4);                    \
    cpa16(dB + 1024 + tid * 4,   gb1 + tid * 4);                           \
    cpa16(dB + 3072 + tid * 4,   gb1 + 1024 + tid * 4);                    \
    asm volatile("cp.async.commit_group;\n" ::: "memory");                 \
} while (0)

    float acc[4][8][4];
    #pragma unroll
    for (int im = 0; im < 4; ++im)
        #pragma unroll
        for (int in = 0; in < 8; ++in)
            #pragma unroll
            for (int r = 0; r < 4; ++r) acc[im][in][r] = 0.f;

    LOAD(0, 0);
    LOAD(1, 1);
    LOAD(2, 2);

    int nh = wn >> 1, nq = wn & 1;

    for (int kt = 0; kt < 64; ++kt) {
        int s = kt & 3;
        asm volatile("cp.async.wait_group 2;\n" ::: "memory");
        __syncthreads();
        if (kt + 3 < 64)
            LOAD((kt + 3) & 3, kt + 3);
        else
            asm volatile("cp.async.commit_group;\n" ::: "memory");

        const float* stg = sm + s * STAGE_FLOATS;

        #pragma unroll
        for (int kk = 0; kk < 2; ++kk) {
            const float* sA  = stg + kk * 1024;
            const float* sBk = stg + 2048 + kk * 2048 + nh * 1024 + nq * 512;

            uint32_t afr[4][4];
            uint32_t bfr[8][2];
            #pragma unroll
            for (int im = 0; im < 4; ++im) {
                float4 v = *(const float4*)&sA[(wm * 4 + im) * 128 + lane * 4];
                afr[im][0] = __float_as_uint(v.x);
                afr[im][1] = __float_as_uint(v.y);
                afr[im][2] = __float_as_uint(v.z);
                afr[im][3] = __float_as_uint(v.w);
            }
            #pragma unroll
            for (int in = 0; in < 8; ++in) {
                float2 v = *(const float2*)&sBk[in * 64 + lane * 2];
                bfr[in][0] = __float_as_uint(v.x);
                bfr[in][1] = __float_as_uint(v.y);
            }
            #pragma unroll
            for (int im = 0; im < 4; ++im)
                #pragma unroll
                for (int in = 0; in < 8; ++in)
                    mma_tf32(acc[im][in], afr[im], bfr[in]);
        }
    }

    // epilogue
    float* Og = Out + (size_t)b * 2048 * 4096;
    int g = lane >> 2, tg = lane & 3;
    #pragma unroll
    for (int im = 0; im < 4; ++im) {
        #pragma unroll
        for (int in = 0; in < 8; ++in) {
            int row = mt * 128 + wm * 64 + im * 16 + g;
            int col = nt2 * 256 + wn * 64 + in * 8 + tg * 2;
            float2 v0 = make_float2(acc[im][in][0], acc[im][in][1]);
            float2 v1 = make_float2(acc[im][in][2], acc[im][in][3]);
            *(float2*)&Og[(size_t)row * 4096 + col]       = v0;
            *(float2*)&Og[(size_t)(row + 8) * 4096 + col] = v1;
        }
    }
#undef LOAD
}

// =====================================================================
extern "C" void kernel_launch(void* const* d_in, const int* in_sizes, int n_in,
                              void* d_out, int out_size)
{
    const float* refer = (const float*)d_in[0];
    const float* sup   = (const float*)d_in[1];
    const float* w_off = (const float*)d_in[2];
    const float* b_off = (const float*)d_in[3];
    const float* w_def = (const float*)d_in[4];
    float* out = (float*)d_out;

    conv_taps_kernel     <<<dim3(8, 4, 16), 256>>>(refer, sup, w_off);
    wdef_frag_kernel     <<<1024,           256>>>(w_def);
    offset_combine_kernel<<<dim3(16, 4),    256>>>(b_off);
    sample_kernel        <<<dim3(16, 4, 4), 256>>>(sup);

    cudaFuncSetAttribute(gemm_kernel, cudaFuncAttributeMaxDynamicSharedMemorySize,
                         GEMM_SMEM);
    gemm_kernel<<<dim3(16, 16, 4), 256, GEMM_SMEM>>>(out);
}

// round 7
// speedup vs baseline: 1.4636x; 1.4636x over previous
#include <cuda_runtime.h>
#include <cuda_fp16.h>
#include <cstdint>

// ---------------- scratch (no mallocs allowed) ----------------
__device__ float g_S[16 * 4 * 18 * 4096];       // conv tap partials, 18.9 MB
__device__ float g_offset[4 * 2 * 4096];        // [b][oc][pix]
// B fp16 mma-fragment order: [b][nt:32][kg:64][n8:16][lane:32][4]  (33.5 MB)
__device__ __half g_Bfrag[4ULL * 32 * 64 * 2048];
// A fp16 mma-fragment order: [mt:16][kg:64][m16:8][lane:32][8]     (4 MB)
__device__ __half g_Afrag[16ULL * 64 * 2048];

#define FMA2(d, a, b, c) \
    asm("fma.rn.f32x2 %0, %1, %2, %3;" : "=l"(d) : "l"(a), "l"(b), "l"(c))

// =====================================================================
// Kernel 1a: tap-decomposed offset conv, stage 1 (channel reduction).
// =====================================================================
__global__ __launch_bounds__(256) void conv_taps_kernel(
    const float* __restrict__ refer, const float* __restrict__ sup,
    const float* __restrict__ w_off)
{
    __shared__ float2 wsh[128 * 18];

    int split = blockIdx.z;
    int b     = blockIdx.y;
    int c0    = split * 128;
    int tid   = threadIdx.x;

    for (int i = tid; i < 128 * 18; i += 256) {
        int c = i / 18, tap = i - c * 18;
        int oc = tap / 9, t9 = tap - oc * 9;
        float w = w_off[((size_t)oc * 2048 + c0 + c) * 9 + t9];
        wsh[i] = make_float2(w, w);
    }
    __syncthreads();

    const float* src = (c0 < 1024)
        ? refer + ((size_t)b * 1024 + c0) * 4096
        : sup   + ((size_t)b * 1024 + (c0 - 1024)) * 4096;

    int px = (blockIdx.x * 256 + tid) * 2;

    unsigned long long acc[18];
    #pragma unroll
    for (int t = 0; t < 18; ++t) acc[t] = 0ull;

    #pragma unroll 2
    for (int c = 0; c < 128; ++c) {
        unsigned long long v =
            *(const unsigned long long*)(src + (size_t)c * 4096 + px);
        const unsigned long long* wp = (const unsigned long long*)&wsh[c * 18];
        #pragma unroll
        for (int t = 0; t < 18; ++t) FMA2(acc[t], wp[t], v, acc[t]);
    }

    float* outb = g_S + (((size_t)split * 4 + b) * 18) * 4096 + px;
    #pragma unroll
    for (int t = 0; t < 18; ++t)
        *(unsigned long long*)(outb + (size_t)t * 4096) = acc[t];
}

// =====================================================================
// Kernel 1b: combine shifted taps + reduce splits -> offsets.
// =====================================================================
__global__ __launch_bounds__(256) void offset_combine_kernel(
    const float* __restrict__ b_off)
{
    int pix = blockIdx.x * 256 + threadIdx.x;
    int b   = blockIdx.y;
    int y = pix >> 6, x = pix & 63;

    #pragma unroll
    for (int oc = 0; oc < 2; ++oc) {
        float acc = b_off[oc];
        #pragma unroll
        for (int ky = 0; ky < 3; ++ky) {
            int yy = y + ky - 1;
            bool vy = (yy >= 0) && (yy < 64);
            #pragma unroll
            for (int kx = 0; kx < 3; ++kx) {
                int xx = x + kx - 1;
                if (vy && xx >= 0 && xx < 64) {
                    int sp = yy * 64 + xx;
                    int tap = oc * 9 + ky * 3 + kx;
                    #pragma unroll 4
                    for (int s = 0; s < 16; ++s)
                        acc += g_S[(((size_t)s * 4 + b) * 18 + tap) * 4096 + sp];
                }
            }
        }
        g_offset[(b * 2 + oc) * 4096 + pix] = acc;
    }
}

// =====================================================================
// Kernel 2: bilinear gather-sample -> B in fp16 mma-fragment order.
// Per k16 group kg: b0 = {B[2tg][g], B[2tg+1][g]}, b1 = {+8}.
// Half index within pixel's 32B block: tg*4 + chi*2 + slot.
// =====================================================================
__global__ __launch_bounds__(256) void sample_kernel(
    const float* __restrict__ sup)
{
    int pix = blockIdx.x * 256 + threadIdx.x;
    int b   = blockIdx.y;
    int cq  = blockIdx.z;

    float o0 = g_offset[(b * 2 + 0) * 4096 + pix];
    float o1 = g_offset[(b * 2 + 1) * 4096 + pix];

    int h = pix >> 6, w = pix & 63;
    float py = o0 + (float)h;
    float px = o1 + (float)w;
    float y0f = floorf(py), x0f = floorf(px);
    float wy = py - y0f, wx = px - x0f;
    int y0 = (int)y0f, x0 = (int)x0f;
    int y1 = y0 + 1,  x1 = x0 + 1;

    float vy0 = (y0 >= 0 && y0 < 64) ? 1.f : 0.f;
    float vy1 = (y1 >= 0 && y1 < 64) ? 1.f : 0.f;
    float vx0 = (x0 >= 0 && x0 < 64) ? 1.f : 0.f;
    float vx1 = (x1 >= 0 && x1 < 64) ? 1.f : 0.f;
    int cy0 = min(max(y0, 0), 63), cy1 = min(max(y1, 0), 63);
    int cx0 = min(max(x0, 0), 63), cx1 = min(max(x1, 0), 63);
    int i00 = cy0 * 64 + cx0, i01 = cy0 * 64 + cx1;
    int i10 = cy1 * 64 + cx0, i11 = cy1 * 64 + cx1;
    float w00 = (1.f - wy) * (1.f - wx) * vy0 * vx0;
    float w01 = (1.f - wy) * wx         * vy0 * vx1;
    float w10 = wy * (1.f - wx)         * vy1 * vx0;
    float w11 = wy * wx                 * vy1 * vx1;

    const float* base = sup + ((size_t)b * 1024 + cq * 256) * 4096;

    int nt = pix >> 7, n8 = (pix >> 3) & 15, g = pix & 7;
    __half* outb = g_Bfrag + (((size_t)b * 32 + nt) * 64) * 2048;

    union { uint4 u[2]; __half hbuf[16]; } pack;

    for (int kg16 = 0; kg16 < 16; ++kg16) {
        int kg = cq * 16 + kg16;
        #pragma unroll
        for (int c = 0; c < 16; ++c) {
            const float* p = base + (size_t)(kg16 * 16 + c) * 4096;
            float r = w00 * p[i00] + w01 * p[i01] + w10 * p[i10] + w11 * p[i11];
            int idx = ((c & 7) >> 1) * 4 + (c >> 3) * 2 + (c & 1);
            pack.hbuf[idx] = __float2half_rn(r);
        }
        __half* dst = outb + ((size_t)kg * 16 + n8) * 128 + g * 16;
        *(uint4*)dst       = pack.u[0];
        *(uint4*)(dst + 8) = pack.u[1];
    }
}

// =====================================================================
// Kernel 2b: w_def -> fp16 A-fragment order.
// a0={A[g][2tg],A[g][2tg+1]}, a1=row+8, a2=k+8, a3=row+8,k+8.
// One thread per (o, kg): 16 floats in, 8 half2 out.
// =====================================================================
__global__ __launch_bounds__(256) void wdef_frag_kernel(
    const float* __restrict__ wd)
{
    int t = blockIdx.x * 256 + threadIdx.x;   // 131072 threads: (o, kg)
    int o = t >> 6, kg = t & 63;
    int mt = o >> 7, mrow = o & 127;
    int m16 = mrow >> 4, r16 = mrow & 15;
    int g = r16 & 7, hi = r16 >> 3;

    const float* src = wd + (size_t)o * 1024 + kg * 16;
    __half2* dst2 = (__half2*)(g_Afrag + (((size_t)mt * 64 + kg) * 8 + m16) * 256);

    #pragma unroll
    for (int p = 0; p < 8; ++p) {
        int c = p * 2;
        int tg = (c & 7) >> 1, chi = c >> 3;
        int lane = g * 4 + tg, reg = hi + 2 * chi;
        dst2[lane * 4 + reg] = __floats2half2_rn(src[c], src[c + 1]);
    }
}

// =====================================================================
// Kernel 3: fp16 mma.sync GEMM (m16n8k16, f32 accum).
// CTA 128x128, warp 64x32 (2x4), k-tile 32. 4-stage cp.async pipeline,
// 16KB/stage (A 8KB + B 8KB). 2 CTAs/SM.
// =====================================================================
__device__ __forceinline__ void mma_f16(float* c, const uint32_t* a, const uint32_t* bb) {
    asm volatile(
        "mma.sync.aligned.m16n8k16.row.col.f32.f16.f16.f32 "
        "{%0,%1,%2,%3},{%4,%5,%6,%7},{%8,%9},{%0,%1,%2,%3};"
        : "+f"(c[0]), "+f"(c[1]), "+f"(c[2]), "+f"(c[3])
        : "r"(a[0]), "r"(a[1]), "r"(a[2]), "r"(a[3]), "r"(bb[0]), "r"(bb[1]));
}

__device__ __forceinline__ void cpa16(char* smem, const char* g) {
    uint32_t s = (uint32_t)__cvta_generic_to_shared(smem);
    asm volatile("cp.async.cg.shared.global [%0], [%1], 16;\n" :: "r"(s), "l"(g) : "memory");
}

static constexpr int STAGE_BYTES = 16384;                // A 8KB + B 8KB
static constexpr int GEMM_SMEM = 4 * STAGE_BYTES;        // 64 KB

__global__ __launch_bounds__(256, 2) void gemm_kernel(float* __restrict__ Out)
{
    extern __shared__ char sm[];

    int tid = threadIdx.x;
    int warp = tid >> 5, lane = tid & 31;
    int wm = warp >> 2, wn = warp & 3;
    int nt = blockIdx.x, mt = blockIdx.y, b = blockIdx.z;

    const char* Ag = (const char*)(g_Afrag + (size_t)mt * 131072);
    const char* Bg = (const char*)(g_Bfrag + ((size_t)b * 32 + nt) * 131072);

    // stage bytes: A [k16:2][m16:8][lane:32][16B] @0, B [k16:2][n8:16][lane:32][8B] @8192
#define LOAD(s, kt) do {                                                   \
    char* dA = sm + (s) * STAGE_BYTES;                                     \
    char* dB = dA + 8192;                                                  \
    const char* ga = Ag + (size_t)(kt) * 8192;                             \
    const char* gb = Bg + (size_t)(kt) * 8192;                             \
    cpa16(dA + tid * 16,        ga + tid * 16);                            \
    cpa16(dA + 4096 + tid * 16, ga + 4096 + tid * 16);                     \
    cpa16(dB + tid * 16,        gb + tid * 16);                            \
    cpa16(dB + 4096 + tid * 16, gb + 4096 + tid * 16);                     \
    asm volatile("cp.async.commit_group;\n" ::: "memory");                 \
} while (0)

    float acc[4][4][4];
    #pragma unroll
    for (int im = 0; im < 4; ++im)
        #pragma unroll
        for (int in = 0; in < 4; ++in)
            #pragma unroll
            for (int r = 0; r < 4; ++r) acc[im][in][r] = 0.f;

    LOAD(0, 0);
    LOAD(1, 1);
    LOAD(2, 2);

    for (int kt = 0; kt < 32; ++kt) {
        int s = kt & 3;
        asm volatile("cp.async.wait_group 2;\n" ::: "memory");
        __syncthreads();
        if (kt + 3 < 32)
            LOAD((kt + 3) & 3, kt + 3);
        else
            asm volatile("cp.async.commit_group;\n" ::: "memory");

        const char* stg = sm + s * STAGE_BYTES;

        #pragma unroll
        for (int kk = 0; kk < 2; ++kk) {
            uint32_t afr[4][4];
            uint32_t bfr[4][2];
            #pragma unroll
            for (int im = 0; im < 4; ++im) {
                uint4 v = *(const uint4*)(stg + kk * 4096 + (wm * 4 + im) * 512 + lane * 16);
                afr[im][0] = v.x; afr[im][1] = v.y;
                afr[im][2] = v.z; afr[im][3] = v.w;
            }
            #pragma unroll
            for (int in = 0; in < 4; ++in) {
                uint2 v = *(const uint2*)(stg + 8192 + kk * 4096 + (wn * 4 + in) * 256 + lane * 8);
                bfr[in][0] = v.x; bfr[in][1] = v.y;
            }
            #pragma unroll
            for (int im = 0; im < 4; ++im)
                #pragma unroll
                for (int in = 0; in < 4; ++in)
                    mma_f16(acc[im][in], afr[im], bfr[in]);
        }
    }

    // epilogue: c0=C[g][2tg], c1=C[g][2tg+1], c2/c3 at row+8
    float* Og = Out + (size_t)b * 2048 * 4096;
    int g = lane >> 2, tg = lane & 3;
    #pragma unroll
    for (int im = 0; im < 4; ++im) {
        #pragma unroll
        for (int in = 0; in < 4; ++in) {
            int row = mt * 128 + wm * 64 + im * 16 + g;
            int col = nt * 128 + wn * 32 + in * 8 + tg * 2;
            float2 v0 = make_float2(acc[im][in][0], acc[im][in][1]);
            float2 v1 = make_float2(acc[im][in][2], acc[im][in][3]);
            *(float2*)&Og[(size_t)row * 4096 + col]       = v0;
            *(float2*)&Og[(size_t)(row + 8) * 4096 + col] = v1;
        }
    }
#undef LOAD
}

// =====================================================================
extern "C" void kernel_launch(void* const* d_in, const int* in_sizes, int n_in,
                              void* d_out, int out_size)
{
    const float* refer = (const float*)d_in[0];
    const float* sup   = (const float*)d_in[1];
    const float* w_off = (const float*)d_in[2];
    const float* b_off = (const float*)d_in[3];
    const float* w_def = (const float*)d_in[4];
    float* out = (float*)d_out;

    conv_taps_kernel     <<<dim3(8, 4, 16), 256>>>(refer, sup, w_off);
    wdef_frag_kernel     <<<512,            256>>>(w_def);
    offset_combine_kernel<<<dim3(16, 4),    256>>>(b_off);
    sample_kernel        <<<dim3(16, 4, 4), 256>>>(sup);

    cudaFuncSetAttribute(gemm_kernel, cudaFuncAttributeMaxDynamicSharedMemorySize,
                         GEMM_SMEM);
    gemm_kernel<<<dim3(32, 16, 4), 256, GEMM_SMEM>>>(out);
}

// round 8
// speedup vs baseline: 1.5989x; 1.0924x over previous
#include <cuda_runtime.h>
#include <cuda_fp16.h>
#include <cstdint>

// ---------------- scratch (no mallocs allowed) ----------------
__device__ float g_S[32 * 4 * 18 * 4096];       // conv tap partials, 37.7 MB
__device__ float g_offset[4 * 2 * 4096];        // [b][oc][pix]
// B fp16 mma-fragment order: [b][nt:32][kg:64][n8:16][lane:32][8]  (33.5 MB)
__device__ __half g_Bfrag[4ULL * 32 * 64 * 2048];
// A fp16 mma-fragment order: [mt:16][kg:64][m16:8][lane:32][8]     (4 MB)
__device__ __half g_Afrag[16ULL * 64 * 2048];

#define FMA2(d, a, b, c) \
    asm("fma.rn.f32x2 %0, %1, %2, %3;" : "=l"(d) : "l"(a), "l"(b), "l"(c))

// =====================================================================
// Kernel 1a: tap-decomposed offset conv, stage 1 (channel reduction).
// 32 channel splits of 64 channels each.
// =====================================================================
__global__ __launch_bounds__(256) void conv_taps_kernel(
    const float* __restrict__ refer, const float* __restrict__ sup,
    const float* __restrict__ w_off)
{
    __shared__ float2 wsh[64 * 18];

    int split = blockIdx.z;
    int b     = blockIdx.y;
    int c0    = split * 64;
    int tid   = threadIdx.x;

    for (int i = tid; i < 64 * 18; i += 256) {
        int c = i / 18, tap = i - c * 18;
        int oc = tap / 9, t9 = tap - oc * 9;
        float w = w_off[((size_t)oc * 2048 + c0 + c) * 9 + t9];
        wsh[i] = make_float2(w, w);
    }
    __syncthreads();

    const float* src = (c0 < 1024)
        ? refer + ((size_t)b * 1024 + c0) * 4096
        : sup   + ((size_t)b * 1024 + (c0 - 1024)) * 4096;

    int px = (blockIdx.x * 256 + tid) * 2;

    unsigned long long acc[18];
    #pragma unroll
    for (int t = 0; t < 18; ++t) acc[t] = 0ull;

    #pragma unroll 2
    for (int c = 0; c < 64; ++c) {
        unsigned long long v =
            *(const unsigned long long*)(src + (size_t)c * 4096 + px);
        const unsigned long long* wp = (const unsigned long long*)&wsh[c * 18];
        #pragma unroll
        for (int t = 0; t < 18; ++t) FMA2(acc[t], wp[t], v, acc[t]);
    }

    float* outb = g_S + (((size_t)split * 4 + b) * 18) * 4096 + px;
    #pragma unroll
    for (int t = 0; t < 18; ++t)
        *(unsigned long long*)(outb + (size_t)t * 4096) = acc[t];
}

// =====================================================================
// Kernel 1b: combine shifted taps + reduce 32 splits -> offsets.
// =====================================================================
__global__ __launch_bounds__(256) void offset_combine_kernel(
    const float* __restrict__ b_off)
{
    int pix = blockIdx.x * 256 + threadIdx.x;
    int b   = blockIdx.y;
    int y = pix >> 6, x = pix & 63;

    #pragma unroll
    for (int oc = 0; oc < 2; ++oc) {
        float acc = b_off[oc];
        #pragma unroll
        for (int ky = 0; ky < 3; ++ky) {
            int yy = y + ky - 1;
            bool vy = (yy >= 0) && (yy < 64);
            #pragma unroll
            for (int kx = 0; kx < 3; ++kx) {
                int xx = x + kx - 1;
                if (vy && xx >= 0 && xx < 64) {
                    int sp = yy * 64 + xx;
                    int tap = oc * 9 + ky * 3 + kx;
                    #pragma unroll 8
                    for (int s = 0; s < 32; ++s)
                        acc += g_S[(((size_t)s * 4 + b) * 18 + tap) * 4096 + sp];
                }
            }
        }
        g_offset[(b * 2 + oc) * 4096 + pix] = acc;
    }
}

// =====================================================================
// Kernel 2: bilinear gather-sample -> B in fp16 mma-fragment order.
// Grid (16 pix strips, 4 batch, 16 channel-64 groups) = 1024 CTAs.
// =====================================================================
__global__ __launch_bounds__(256) void sample_kernel(
    const float* __restrict__ sup)
{
    int pix = blockIdx.x * 256 + threadIdx.x;
    int b   = blockIdx.y;
    int cq  = blockIdx.z;          // 0..15, 64 channels each

    float o0 = g_offset[(b * 2 + 0) * 4096 + pix];
    float o1 = g_offset[(b * 2 + 1) * 4096 + pix];

    int h = pix >> 6, w = pix & 63;
    float py = o0 + (float)h;
    float px = o1 + (float)w;
    float y0f = floorf(py), x0f = floorf(px);
    float wy = py - y0f, wx = px - x0f;
    int y0 = (int)y0f, x0 = (int)x0f;
    int y1 = y0 + 1,  x1 = x0 + 1;

    float vy0 = (y0 >= 0 && y0 < 64) ? 1.f : 0.f;
    float vy1 = (y1 >= 0 && y1 < 64) ? 1.f : 0.f;
    float vx0 = (x0 >= 0 && x0 < 64) ? 1.f : 0.f;
    float vx1 = (x1 >= 0 && x1 < 64) ? 1.f : 0.f;
    int cy0 = min(max(y0, 0), 63), cy1 = min(max(y1, 0), 63);
    int cx0 = min(max(x0, 0), 63), cx1 = min(max(x1, 0), 63);
    int i00 = cy0 * 64 + cx0, i01 = cy0 * 64 + cx1;
    int i10 = cy1 * 64 + cx0, i11 = cy1 * 64 + cx1;
    float w00 = (1.f - wy) * (1.f - wx) * vy0 * vx0;
    float w01 = (1.f - wy) * wx         * vy0 * vx1;
    float w10 = wy * (1.f - wx)         * vy1 * vx0;
    float w11 = wy * wx                 * vy1 * vx1;

    const float* base = sup + ((size_t)b * 1024 + cq * 64) * 4096;

    int nt = pix >> 7, n8 = (pix >> 3) & 15, g = pix & 7;
    __half* outb = g_Bfrag + (((size_t)b * 32 + nt) * 64) * 2048;

    union { uint4 u[2]; __half hbuf[16]; } pack;

    #pragma unroll
    for (int kg16 = 0; kg16 < 4; ++kg16) {
        int kg = cq * 4 + kg16;
        #pragma unroll
        for (int c = 0; c < 16; ++c) {
            const float* p = base + (size_t)(kg16 * 16 + c) * 4096;
            float r = w00 * p[i00] + w01 * p[i01] + w10 * p[i10] + w11 * p[i11];
            int idx = ((c & 7) >> 1) * 4 + (c >> 3) * 2 + (c & 1);
            pack.hbuf[idx] = __float2half_rn(r);
        }
        __half* dst = outb + ((size_t)kg * 16 + n8) * 128 + g * 16;
        *(uint4*)dst       = pack.u[0];
        *(uint4*)(dst + 8) = pack.u[1];
    }
}

// =====================================================================
// Kernel 2b: w_def -> fp16 A-fragment order.
// =====================================================================
__global__ __launch_bounds__(256) void wdef_frag_kernel(
    const float* __restrict__ wd)
{
    int t = blockIdx.x * 256 + threadIdx.x;   // 131072 threads: (o, kg)
    int o = t >> 6, kg = t & 63;
    int mt = o >> 7, mrow = o & 127;
    int m16 = mrow >> 4, r16 = mrow & 15;
    int g = r16 & 7, hi = r16 >> 3;

    const float* src = wd + (size_t)o * 1024 + kg * 16;
    __half2* dst2 = (__half2*)(g_Afrag + (((size_t)mt * 64 + kg) * 8 + m16) * 256);

    #pragma unroll
    for (int p = 0; p < 8; ++p) {
        int c = p * 2;
        int tg = (c & 7) >> 1, chi = c >> 3;
        int lane = g * 4 + tg, reg = hi + 2 * chi;
        dst2[lane * 4 + reg] = __floats2half2_rn(src[c], src[c + 1]);
    }
}

// =====================================================================
// Kernel 3: fp16 mma.sync GEMM (m16n8k16, f32 accum).
// CTA 128x128, warp 64x32 (2x4), k-tile 32. 6-stage cp.async pipeline,
// 16KB/stage. 2 CTAs/SM.
// =====================================================================
__device__ __forceinline__ void mma_f16(float* c, const uint32_t* a, const uint32_t* bb) {
    asm volatile(
        "mma.sync.aligned.m16n8k16.row.col.f32.f16.f16.f32 "
        "{%0,%1,%2,%3},{%4,%5,%6,%7},{%8,%9},{%0,%1,%2,%3};"
        : "+f"(c[0]), "+f"(c[1]), "+f"(c[2]), "+f"(c[3])
        : "r"(a[0]), "r"(a[1]), "r"(a[2]), "r"(a[3]), "r"(bb[0]), "r"(bb[1]));
}

__device__ __forceinline__ void cpa16(char* smem, const char* g) {
    uint32_t s = (uint32_t)__cvta_generic_to_shared(smem);
    asm volatile("cp.async.cg.shared.global [%0], [%1], 16;\n" :: "r"(s), "l"(g) : "memory");
}

static constexpr int STAGE_BYTES = 16384;                // A 8KB + B 8KB
static constexpr int N_STAGES = 6;
static constexpr int GEMM_SMEM = N_STAGES * STAGE_BYTES; // 96 KB

__global__ __launch_bounds__(256, 2) void gemm_kernel(float* __restrict__ Out)
{
    extern __shared__ char sm[];

    int tid = threadIdx.x;
    int warp = tid >> 5, lane = tid & 31;
    int wm = warp >> 2, wn = warp & 3;
    int nt = blockIdx.x, mt = blockIdx.y, b = blockIdx.z;

    const char* Ag = (const char*)(g_Afrag + (size_t)mt * 131072);
    const char* Bg = (const char*)(g_Bfrag + ((size_t)b * 32 + nt) * 131072);

#define LOAD(s, kt) do {                                                   \
    char* dA = sm + (s) * STAGE_BYTES;                                     \
    char* dB = dA + 8192;                                                  \
    const char* ga = Ag + (size_t)(kt) * 8192;                             \
    const char* gb = Bg + (size_t)(kt) * 8192;                             \
    cpa16(dA + tid * 16,        ga + tid * 16);                            \
    cpa16(dA + 4096 + tid * 16, ga + 4096 + tid * 16);                     \
    cpa16(dB + tid * 16,        gb + tid * 16);                            \
    cpa16(dB + 4096 + tid * 16, gb + 4096 + tid * 16);                     \
    asm volatile("cp.async.commit_group;\n" ::: "memory");                 \
} while (0)

    float acc[4][4][4];
    #pragma unroll
    for (int im = 0; im < 4; ++im)
        #pragma unroll
        for (int in = 0; in < 4; ++in)
            #pragma unroll
            for (int r = 0; r < 4; ++r) acc[im][in][r] = 0.f;

    LOAD(0, 0);
    LOAD(1, 1);
    LOAD(2, 2);
    LOAD(3, 3);
    LOAD(4, 4);

    int s = 0, sp = 5;          // current stage, next stage to fill

    for (int kt = 0; kt < 32; ++kt) {
        asm volatile("cp.async.wait_group 4;\n" ::: "memory");
        __syncthreads();
        if (kt + 5 < 32)
            LOAD(sp, kt + 5);
        else
            asm volatile("cp.async.commit_group;\n" ::: "memory");
        if (++sp == N_STAGES) sp = 0;

        const char* stg = sm + s * STAGE_BYTES;
        if (++s == N_STAGES) s = 0;

        #pragma unroll
        for (int kk = 0; kk < 2; ++kk) {
            uint32_t afr[4][4];
            uint32_t bfr[4][2];
            #pragma unroll
            for (int im = 0; im < 4; ++im) {
                uint4 v = *(const uint4*)(stg + kk * 4096 + (wm * 4 + im) * 512 + lane * 16);
                afr[im][0] = v.x; afr[im][1] = v.y;
                afr[im][2] = v.z; afr[im][3] = v.w;
            }
            #pragma unroll
            for (int in = 0; in < 4; ++in) {
                uint2 v = *(const uint2*)(stg + 8192 + kk * 4096 + (wn * 4 + in) * 256 + lane * 8);
                bfr[in][0] = v.x; bfr[in][1] = v.y;
            }
            #pragma unroll
            for (int im = 0; im < 4; ++im)
                #pragma unroll
                for (int in = 0; in < 4; ++in)
                    mma_f16(acc[im][in], afr[im], bfr[in]);
        }
    }

    // epilogue
    float* Og = Out + (size_t)b * 2048 * 4096;
    int g = lane >> 2, tg = lane & 3;
    #pragma unroll
    for (int im = 0; im < 4; ++im) {
        #pragma unroll
        for (int in = 0; in < 4; ++in) {
            int row = mt * 128 + wm * 64 + im * 16 + g;
            int col = nt * 128 + wn * 32 + in * 8 + tg * 2;
            float2 v0 = make_float2(acc[im][in][0], acc[im][in][1]);
            float2 v1 = make_float2(acc[im][in][2], acc[im][in][3]);
            *(float2*)&Og[(size_t)row * 4096 + col]       = v0;
            *(float2*)&Og[(size_t)(row + 8) * 4096 + col] = v1;
        }
    }
#undef LOAD
}

// =====================================================================
extern "C" void kernel_launch(void* const* d_in, const int* in_sizes, int n_in,
                              void* d_out, int out_size)
{
    const float* refer = (const float*)d_in[0];
    const float* sup   = (const float*)d_in[1];
    const float* w_off = (const float*)d_in[2];
    const float* b_off = (const float*)d_in[3];
    const float* w_def = (const float*)d_in[4];
    float* out = (float*)d_out;

    conv_taps_kernel     <<<dim3(8, 4, 32),  256>>>(refer, sup, w_off);
    wdef_frag_kernel     <<<512,             256>>>(w_def);
    offset_combine_kernel<<<dim3(16, 4),     256>>>(b_off);
    sample_kernel        <<<dim3(16, 4, 16), 256>>>(sup);

    cudaFuncSetAttribute(gemm_kernel, cudaFuncAttributeMaxDynamicSharedMemorySize,
                         GEMM_SMEM);
    gemm_kernel<<<dim3(32, 16, 4), 256, GEMM_SMEM>>>(out);
}

// round 9
// speedup vs baseline: 1.6404x; 1.0259x over previous
#include <cuda_runtime.h>
#include <cuda_fp16.h>
#include <cstdint>

// ---------------- scratch (no mallocs allowed) ----------------
__device__ float g_S[32 * 4 * 18 * 4096];       // conv tap partials, 37.7 MB
__device__ float g_offset[4 * 2 * 4096];        // [b][oc][pix]
// B fp16 mma-fragment order: [b][nt:32][kg:64][n8:16][lane:32][8]  (33.5 MB)
__device__ __half g_Bfrag[4ULL * 32 * 64 * 2048];
// A fp16 mma-fragment order: [mt:16][kg:64][m16:8][lane:32][8]     (4 MB)
__device__ __half g_Afrag[16ULL * 64 * 2048];

#define FMA2(d, a, b, c) \
    asm("fma.rn.f32x2 %0, %1, %2, %3;" : "=l"(d) : "l"(a), "l"(b), "l"(c))

// =====================================================================
// Kernel 1: fused (a) tap-decomposed offset conv channel reduction
// [blockIdx.z 0..31] and (b) w_def -> fp16 A-fragment repack
// [blockIdx.z 32..33].
// =====================================================================
__global__ __launch_bounds__(256) void conv_wdef_kernel(
    const float* __restrict__ refer, const float* __restrict__ sup,
    const float* __restrict__ w_off, const float* __restrict__ wd)
{
    if (blockIdx.z >= 32) {
        // ---- w_def repack: 131072 items over 64 blocks x 8 iters ----
        int bid = (blockIdx.z - 32) * 32 + blockIdx.y * 8 + blockIdx.x;
        #pragma unroll
        for (int it = 0; it < 8; ++it) {
            int t = (bid * 8 + it) * 256 + threadIdx.x;   // (o, kg)
            int o = t >> 6, kg = t & 63;
            int mt = o >> 7, mrow = o & 127;
            int m16 = mrow >> 4, r16 = mrow & 15;
            int g = r16 & 7, hi = r16 >> 3;

            const float* src = wd + (size_t)o * 1024 + kg * 16;
            __half2* dst2 =
                (__half2*)(g_Afrag + (((size_t)mt * 64 + kg) * 8 + m16) * 256);

            #pragma unroll
            for (int p = 0; p < 8; ++p) {
                int c = p * 2;
                int tg = (c & 7) >> 1, chi = c >> 3;
                int lane = g * 4 + tg, reg = hi + 2 * chi;
                dst2[lane * 4 + reg] = __floats2half2_rn(src[c], src[c + 1]);
            }
        }
        return;
    }

    // ---- conv tap reduction: 64 channels per split ----
    __shared__ float2 wsh[64 * 18];

    int split = blockIdx.z;
    int b     = blockIdx.y;
    int c0    = split * 64;
    int tid   = threadIdx.x;

    for (int i = tid; i < 64 * 18; i += 256) {
        int c = i / 18, tap = i - c * 18;
        int oc = tap / 9, t9 = tap - oc * 9;
        float w = w_off[((size_t)oc * 2048 + c0 + c) * 9 + t9];
        wsh[i] = make_float2(w, w);
    }
    __syncthreads();

    const float* src = (c0 < 1024)
        ? refer + ((size_t)b * 1024 + c0) * 4096
        : sup   + ((size_t)b * 1024 + (c0 - 1024)) * 4096;

    int px = (blockIdx.x * 256 + tid) * 2;

    unsigned long long acc[18];
    #pragma unroll
    for (int t = 0; t < 18; ++t) acc[t] = 0ull;

    #pragma unroll 2
    for (int c = 0; c < 64; ++c) {
        unsigned long long v =
            *(const unsigned long long*)(src + (size_t)c * 4096 + px);
        const unsigned long long* wp = (const unsigned long long*)&wsh[c * 18];
        #pragma unroll
        for (int t = 0; t < 18; ++t) FMA2(acc[t], wp[t], v, acc[t]);
    }

    float* outb = g_S + (((size_t)split * 4 + b) * 18) * 4096 + px;
    #pragma unroll
    for (int t = 0; t < 18; ++t)
        *(unsigned long long*)(outb + (size_t)t * 4096) = acc[t];
}

// =====================================================================
// Kernel 2: combine shifted taps + reduce 32 splits -> offsets.
// 4 threads per pixel (each 8 splits), shfl reduce. Grid (64,4).
// =====================================================================
__global__ __launch_bounds__(256) void offset_combine_kernel(
    const float* __restrict__ b_off)
{
    int b  = blockIdx.y;
    int pl = threadIdx.x >> 2;          // 0..63 pixel within block
    int q  = threadIdx.x & 3;           // split quarter: splits q*8..q*8+7
    int pix = blockIdx.x * 64 + pl;
    int y = pix >> 6, x = pix & 63;

    float a0 = 0.f, a1 = 0.f;
    int s0 = q * 8;

    #pragma unroll
    for (int ky = 0; ky < 3; ++ky) {
        int yy = y + ky - 1;
        bool vy = (yy >= 0) && (yy < 64);
        #pragma unroll
        for (int kx = 0; kx < 3; ++kx) {
            int xx = x + kx - 1;
            if (vy && xx >= 0 && xx < 64) {
                int sp = yy * 64 + xx;
                int t9 = ky * 3 + kx;
                #pragma unroll
                for (int ds = 0; ds < 8; ++ds) {
                    int s = s0 + ds;
                    const float* Sb = g_S + (((size_t)s * 4 + b) * 18) * 4096 + sp;
                    a0 += Sb[(size_t)t9 * 4096];
                    a1 += Sb[(size_t)(9 + t9) * 4096];
                }
            }
        }
    }

    a0 += __shfl_xor_sync(0xFFFFFFFF, a0, 1);
    a0 += __shfl_xor_sync(0xFFFFFFFF, a0, 2);
    a1 += __shfl_xor_sync(0xFFFFFFFF, a1, 1);
    a1 += __shfl_xor_sync(0xFFFFFFFF, a1, 2);

    if (q == 0) {
        g_offset[(b * 2 + 0) * 4096 + pix] = a0 + b_off[0];
        g_offset[(b * 2 + 1) * 4096 + pix] = a1 + b_off[1];
    }
}

// =====================================================================
// Kernel 3: bilinear gather-sample -> B in fp16 mma-fragment order.
// Grid (16 pix strips, 4 batch, 16 channel-64 groups) = 1024 CTAs.
// =====================================================================
__global__ __launch_bounds__(256) void sample_kernel(
    const float* __restrict__ sup)
{
    int pix = blockIdx.x * 256 + threadIdx.x;
    int b   = blockIdx.y;
    int cq  = blockIdx.z;          // 0..15, 64 channels each

    float o0 = g_offset[(b * 2 + 0) * 4096 + pix];
    float o1 = g_offset[(b * 2 + 1) * 4096 + pix];

    int h = pix >> 6, w = pix & 63;
    float py = o0 + (float)h;
    float px = o1 + (float)w;
    float y0f = floorf(py), x0f = floorf(px);
    float wy = py - y0f, wx = px - x0f;
    int y0 = (int)y0f, x0 = (int)x0f;
    int y1 = y0 + 1,  x1 = x0 + 1;

    float vy0 = (y0 >= 0 && y0 < 64) ? 1.f : 0.f;
    float vy1 = (y1 >= 0 && y1 < 64) ? 1.f : 0.f;
    float vx0 = (x0 >= 0 && x0 < 64) ? 1.f : 0.f;
    float vx1 = (x1 >= 0 && x1 < 64) ? 1.f : 0.f;
    int cy0 = min(max(y0, 0), 63), cy1 = min(max(y1, 0), 63);
    int cx0 = min(max(x0, 0), 63), cx1 = min(max(x1, 0), 63);
    int i00 = cy0 * 64 + cx0, i01 = cy0 * 64 + cx1;
    int i10 = cy1 * 64 + cx0, i11 = cy1 * 64 + cx1;
    float w00 = (1.f - wy) * (1.f - wx) * vy0 * vx0;
    float w01 = (1.f - wy) * wx         * vy0 * vx1;
    float w10 = wy * (1.f - wx)         * vy1 * vx0;
    float w11 = wy * wx                 * vy1 * vx1;

    const float* base = sup + ((size_t)b * 1024 + cq * 64) * 4096;

    int nt = pix >> 7, n8 = (pix >> 3) & 15, g = pix & 7;
    __half* outb = g_Bfrag + (((size_t)b * 32 + nt) * 64) * 2048;

    union { uint4 u[2]; __half hbuf[16]; } pack;

    #pragma unroll
    for (int kg16 = 0; kg16 < 4; ++kg16) {
        int kg = cq * 4 + kg16;
        #pragma unroll
        for (int c = 0; c < 16; ++c) {
            const float* p = base + (size_t)(kg16 * 16 + c) * 4096;
            float r = w00 * p[i00] + w01 * p[i01] + w10 * p[i10] + w11 * p[i11];
            int idx = ((c & 7) >> 1) * 4 + (c >> 3) * 2 + (c & 1);
            pack.hbuf[idx] = __float2half_rn(r);
        }
        __half* dst = outb + ((size_t)kg * 16 + n8) * 128 + g * 16;
        *(uint4*)dst       = pack.u[0];
        *(uint4*)(dst + 8) = pack.u[1];
    }
}

// =====================================================================
// Kernel 4: fp16 mma.sync GEMM (m16n8k16, f32 accum).
// CTA 128x128, warp 64x32 (2x4), k-tile 64. 3-stage cp.async pipeline,
// 32KB/stage (A 16KB + B 16KB). 2 CTAs/SM.
// =====================================================================
__device__ __forceinline__ void mma_f16(float* c, const uint32_t* a, const uint32_t* bb) {
    asm volatile(
        "mma.sync.aligned.m16n8k16.row.col.f32.f16.f16.f32 "
        "{%0,%1,%2,%3},{%4,%5,%6,%7},{%8,%9},{%0,%1,%2,%3};"
        : "+f"(c[0]), "+f"(c[1]), "+f"(c[2]), "+f"(c[3])
        : "r"(a[0]), "r"(a[1]), "r"(a[2]), "r"(a[3]), "r"(bb[0]), "r"(bb[1]));
}

__device__ __forceinline__ void cpa16(char* smem, const char* g) {
    uint32_t s = (uint32_t)__cvta_generic_to_shared(smem);
    asm volatile("cp.async.cg.shared.global [%0], [%1], 16;\n" :: "r"(s), "l"(g) : "memory");
}

static constexpr int STAGE_BYTES = 32768;                // A 16KB + B 16KB
static constexpr int N_STAGES = 3;
static constexpr int GEMM_SMEM = N_STAGES * STAGE_BYTES; // 96 KB

__global__ __launch_bounds__(256, 2) void gemm_kernel(float* __restrict__ Out)
{
    extern __shared__ char sm[];

    int tid = threadIdx.x;
    int warp = tid >> 5, lane = tid & 31;
    int wm = warp >> 2, wn = warp & 3;
    int nt = blockIdx.x, mt = blockIdx.y, b = blockIdx.z;

    const char* Ag = (const char*)(g_Afrag + (size_t)mt * 131072);
    const char* Bg = (const char*)(g_Bfrag + ((size_t)b * 32 + nt) * 131072);

    // stage: A [k16:4][m16:8][lane:32][16B] @0, B [k16:4][n8:16][lane:32][8B] @16384
#define LOAD(s, kt) do {                                                   \
    char* dA = sm + (s) * STAGE_BYTES;                                     \
    char* dB = dA + 16384;                                                 \
    const char* ga = Ag + (size_t)(kt) * 16384;                            \
    const char* gb = Bg + (size_t)(kt) * 16384;                            \
    _Pragma("unroll")                                                      \
    for (int i = 0; i < 4; ++i) {                                          \
        cpa16(dA + i * 4096 + tid * 16, ga + i * 4096 + tid * 16);         \
        cpa16(dB + i * 4096 + tid * 16, gb + i * 4096 + tid * 16);         \
    }                                                                      \
    asm volatile("cp.async.commit_group;\n" ::: "memory");                 \
} while (0)

    float acc[4][4][4];
    #pragma unroll
    for (int im = 0; im < 4; ++im)
        #pragma unroll
        for (int in = 0; in < 4; ++in)
            #pragma unroll
            for (int r = 0; r < 4; ++r) acc[im][in][r] = 0.f;

    LOAD(0, 0);
    LOAD(1, 1);

    for (int kt = 0; kt < 16; ++kt) {
        int s = kt % 3;
        asm volatile("cp.async.wait_group 1;\n" ::: "memory");
        __syncthreads();
        if (kt + 2 < 16)
            LOAD((kt + 2) % 3, kt + 2);
        else
            asm volatile("cp.async.commit_group;\n" ::: "memory");

        const char* stg = sm + s * STAGE_BYTES;

        #pragma unroll
        for (int kk = 0; kk < 4; ++kk) {
            uint32_t afr[4][4];
            uint32_t bfr[4][2];
            #pragma unroll
            for (int im = 0; im < 4; ++im) {
                uint4 v = *(const uint4*)(stg + kk * 4096 + (wm * 4 + im) * 512 + lane * 16);
                afr[im][0] = v.x; afr[im][1] = v.y;
                afr[im][2] = v.z; afr[im][3] = v.w;
            }
            #pragma unroll
            for (int in = 0; in < 4; ++in) {
                uint2 v = *(const uint2*)(stg + 16384 + kk * 4096 + (wn * 4 + in) * 256 + lane * 8);
                bfr[in][0] = v.x; bfr[in][1] = v.y;
            }
            #pragma unroll
            for (int im = 0; im < 4; ++im)
                #pragma unroll
                for (int in = 0; in < 4; ++in)
                    mma_f16(acc[im][in], afr[im], bfr[in]);
        }
    }

    // epilogue
    float* Og = Out + (size_t)b * 2048 * 4096;
    int g = lane >> 2, tg = lane & 3;
    #pragma unroll
    for (int im = 0; im < 4; ++im) {
        #pragma unroll
        for (int in = 0; in < 4; ++in) {
            int row = mt * 128 + wm * 64 + im * 16 + g;
            int col = nt * 128 + wn * 32 + in * 8 + tg * 2;
            float2 v0 = make_float2(acc[im][in][0], acc[im][in][1]);
            float2 v1 = make_float2(acc[im][in][2], acc[im][in][3]);
            *(float2*)&Og[(size_t)row * 4096 + col]       = v0;
            *(float2*)&Og[(size_t)(row + 8) * 4096 + col] = v1;
        }
    }
#undef LOAD
}

// =====================================================================
extern "C" void kernel_launch(void* const* d_in, const int* in_sizes, int n_in,
                              void* d_out, int out_size)
{
    const float* refer = (const float*)d_in[0];
    const float* sup   = (const float*)d_in[1];
    const float* w_off = (const float*)d_in[2];
    const float* b_off = (const float*)d_in[3];
    const float* w_def = (const float*)d_in[4];
    float* out = (float*)d_out;

    conv_wdef_kernel     <<<dim3(8, 4, 34),  256>>>(refer, sup, w_off, w_def);
    offset_combine_kernel<<<dim3(64, 4),     256>>>(b_off);
    sample_kernel        <<<dim3(16, 4, 16), 256>>>(sup);

    cudaFuncSetAttribute(gemm_kernel, cudaFuncAttributeMaxDynamicSharedMemorySize,
                         GEMM_SMEM);
    gemm_kernel<<<dim3(32, 16, 4), 256, GEMM_SMEM>>>(out);
}

// round 10
// speedup vs baseline: 1.7075x; 1.0409x over previous
#include <cuda_runtime.h>
#include <cuda_fp16.h>
#include <cstdint>

// ---------------- scratch (no mallocs allowed) ----------------
__device__ float g_S[32 * 4 * 18 * 4096];       // conv tap partials, 37.7 MB
__device__ float g_offset[4 * 2 * 4096];        // [b][oc][pix]
// B fp16 mma-fragment order: [b][nt:32][kg:64][n8:16][lane:32][4]  (33.5 MB)
__device__ __half g_Bfrag[4ULL * 32 * 64 * 2048];
// A fp16 mma-fragment order: [mt:16][kg:64][m16:8][lane:32][8]     (4 MB)
__device__ __half g_Afrag[16ULL * 64 * 2048];

#define FMA2(d, a, b, c) \
    asm("fma.rn.f32x2 %0, %1, %2, %3;" : "=l"(d) : "l"(a), "l"(b), "l"(c))

// =====================================================================
// Kernel 1: fused (a) tap-decomposed offset conv channel reduction
// [blockIdx.z 0..31] and (b) w_def -> fp16 A-fragment repack
// [blockIdx.z 32..33].
// =====================================================================
__global__ __launch_bounds__(256) void conv_wdef_kernel(
    const float* __restrict__ refer, const float* __restrict__ sup,
    const float* __restrict__ w_off, const float* __restrict__ wd)
{
    if (blockIdx.z >= 32) {
        // ---- w_def repack: 131072 items over 64 blocks x 8 iters ----
        int bid = (blockIdx.z - 32) * 32 + blockIdx.y * 8 + blockIdx.x;
        #pragma unroll
        for (int it = 0; it < 8; ++it) {
            int t = (bid * 8 + it) * 256 + threadIdx.x;   // (o, kg)
            int o = t >> 6, kg = t & 63;
            int mt = o >> 7, mrow = o & 127;
            int m16 = mrow >> 4, r16 = mrow & 15;
            int g = r16 & 7, hi = r16 >> 3;

            const float* src = wd + (size_t)o * 1024 + kg * 16;
            __half2* dst2 =
                (__half2*)(g_Afrag + (((size_t)mt * 64 + kg) * 8 + m16) * 256);

            #pragma unroll
            for (int p = 0; p < 8; ++p) {
                int c = p * 2;
                int tg = (c & 7) >> 1, chi = c >> 3;
                int lane = g * 4 + tg, reg = hi + 2 * chi;
                dst2[lane * 4 + reg] = __floats2half2_rn(src[c], src[c + 1]);
            }
        }
        return;
    }

    // ---- conv tap reduction: 64 channels per split ----
    __shared__ float2 wsh[64 * 18];

    int split = blockIdx.z;
    int b     = blockIdx.y;
    int c0    = split * 64;
    int tid   = threadIdx.x;

    for (int i = tid; i < 64 * 18; i += 256) {
        int c = i / 18, tap = i - c * 18;
        int oc = tap / 9, t9 = tap - oc * 9;
        float w = w_off[((size_t)oc * 2048 + c0 + c) * 9 + t9];
        wsh[i] = make_float2(w, w);
    }
    __syncthreads();

    const float* src = (c0 < 1024)
        ? refer + ((size_t)b * 1024 + c0) * 4096
        : sup   + ((size_t)b * 1024 + (c0 - 1024)) * 4096;

    int px = (blockIdx.x * 256 + tid) * 2;

    unsigned long long acc[18];
    #pragma unroll
    for (int t = 0; t < 18; ++t) acc[t] = 0ull;

    #pragma unroll 2
    for (int c = 0; c < 64; ++c) {
        unsigned long long v =
            *(const unsigned long long*)(src + (size_t)c * 4096 + px);
        const unsigned long long* wp = (const unsigned long long*)&wsh[c * 18];
        #pragma unroll
        for (int t = 0; t < 18; ++t) FMA2(acc[t], wp[t], v, acc[t]);
    }

    float* outb = g_S + (((size_t)split * 4 + b) * 18) * 4096 + px;
    #pragma unroll
    for (int t = 0; t < 18; ++t)
        *(unsigned long long*)(outb + (size_t)t * 4096) = acc[t];
}

// =====================================================================
// Kernel 2: combine shifted taps + reduce 32 splits -> offsets.
// 4 threads per pixel (each 8 splits), shfl reduce. Grid (64,4).
// =====================================================================
__global__ __launch_bounds__(256) void offset_combine_kernel(
    const float* __restrict__ b_off)
{
    int b  = blockIdx.y;
    int pl = threadIdx.x >> 2;          // 0..63 pixel within block
    int q  = threadIdx.x & 3;           // split quarter: splits q*8..q*8+7
    int pix = blockIdx.x * 64 + pl;
    int y = pix >> 6, x = pix & 63;

    float a0 = 0.f, a1 = 0.f;
    int s0 = q * 8;

    #pragma unroll
    for (int ky = 0; ky < 3; ++ky) {
        int yy = y + ky - 1;
        bool vy = (yy >= 0) && (yy < 64);
        #pragma unroll
        for (int kx = 0; kx < 3; ++kx) {
            int xx = x + kx - 1;
            if (vy && xx >= 0 && xx < 64) {
                int sp = yy * 64 + xx;
                int t9 = ky * 3 + kx;
                #pragma unroll
                for (int ds = 0; ds < 8; ++ds) {
                    int s = s0 + ds;
                    const float* Sb = g_S + (((size_t)s * 4 + b) * 18) * 4096 + sp;
                    a0 += Sb[(size_t)t9 * 4096];
                    a1 += Sb[(size_t)(9 + t9) * 4096];
                }
            }
        }
    }

    a0 += __shfl_xor_sync(0xFFFFFFFF, a0, 1);
    a0 += __shfl_xor_sync(0xFFFFFFFF, a0, 2);
    a1 += __shfl_xor_sync(0xFFFFFFFF, a1, 1);
    a1 += __shfl_xor_sync(0xFFFFFFFF, a1, 2);

    if (q == 0) {
        g_offset[(b * 2 + 0) * 4096 + pix] = a0 + b_off[0];
        g_offset[(b * 2 + 1) * 4096 + pix] = a1 + b_off[1];
    }
}

// =====================================================================
// Kernel 3: bilinear gather-sample -> B in fp16 mma-fragment order.
// Grid (16 pix strips, 4 batch, 16 channel-64 groups) = 1024 CTAs.
// =====================================================================
__global__ __launch_bounds__(256) void sample_kernel(
    const float* __restrict__ sup)
{
    int pix = blockIdx.x * 256 + threadIdx.x;
    int b   = blockIdx.y;
    int cq  = blockIdx.z;          // 0..15, 64 channels each

    float o0 = g_offset[(b * 2 + 0) * 4096 + pix];
    float o1 = g_offset[(b * 2 + 1) * 4096 + pix];

    int h = pix >> 6, w = pix & 63;
    float py = o0 + (float)h;
    float px = o1 + (float)w;
    float y0f = floorf(py), x0f = floorf(px);
    float wy = py - y0f, wx = px - x0f;
    int y0 = (int)y0f, x0 = (int)x0f;
    int y1 = y0 + 1,  x1 = x0 + 1;

    float vy0 = (y0 >= 0 && y0 < 64) ? 1.f : 0.f;
    float vy1 = (y1 >= 0 && y1 < 64) ? 1.f : 0.f;
    float vx0 = (x0 >= 0 && x0 < 64) ? 1.f : 0.f;
    float vx1 = (x1 >= 0 && x1 < 64) ? 1.f : 0.f;
    int cy0 = min(max(y0, 0), 63), cy1 = min(max(y1, 0), 63);
    int cx0 = min(max(x0, 0), 63), cx1 = min(max(x1, 0), 63);
    int i00 = cy0 * 64 + cx0, i01 = cy0 * 64 + cx1;
    int i10 = cy1 * 64 + cx0, i11 = cy1 * 64 + cx1;
    float w00 = (1.f - wy) * (1.f - wx) * vy0 * vx0;
    float w01 = (1.f - wy) * wx         * vy0 * vx1;
    float w10 = wy * (1.f - wx)         * vy1 * vx0;
    float w11 = wy * wx                 * vy1 * vx1;

    const float* base = sup + ((size_t)b * 1024 + cq * 64) * 4096;

    int nt = pix >> 7, n8 = (pix >> 3) & 15, g = pix & 7;
    __half* outb = g_Bfrag + (((size_t)b * 32 + nt) * 64) * 2048;

    union { uint4 u[2]; __half hbuf[16]; } pack;

    #pragma unroll
    for (int kg16 = 0; kg16 < 4; ++kg16) {
        int kg = cq * 4 + kg16;
        #pragma unroll
        for (int c = 0; c < 16; ++c) {
            const float* p = base + (size_t)(kg16 * 16 + c) * 4096;
            float r = w00 * p[i00] + w01 * p[i01] + w10 * p[i10] + w11 * p[i11];
            int idx = ((c & 7) >> 1) * 4 + (c >> 3) * 2 + (c & 1);
            pack.hbuf[idx] = __float2half_rn(r);
        }
        __half* dst = outb + ((size_t)kg * 16 + n8) * 128 + g * 16;
        *(uint4*)dst       = pack.u[0];
        *(uint4*)(dst + 8) = pack.u[1];
    }
}

// =====================================================================
// Kernel 4: fp16 mma.sync GEMM (m16n8k16, f32 accum).
// 128-thread CTAs: 4 warps (2x2) of 64x64 warp tiles -> CTA 128x128.
// Square warp tiles cut smem operand traffic to 128 B/MMA (crossbar
// was the co-limiter at 64x32). k-tile 64, 3-stage cp.async (96 KB),
// 2 CTAs/SM.
// =====================================================================
__device__ __forceinline__ void mma_f16(float* c, const uint32_t* a, const uint32_t* bb) {
    asm volatile(
        "mma.sync.aligned.m16n8k16.row.col.f32.f16.f16.f32 "
        "{%0,%1,%2,%3},{%4,%5,%6,%7},{%8,%9},{%0,%1,%2,%3};"
        : "+f"(c[0]), "+f"(c[1]), "+f"(c[2]), "+f"(c[3])
        : "r"(a[0]), "r"(a[1]), "r"(a[2]), "r"(a[3]), "r"(bb[0]), "r"(bb[1]));
}

__device__ __forceinline__ void cpa16(char* smem, const char* g) {
    uint32_t s = (uint32_t)__cvta_generic_to_shared(smem);
    asm volatile("cp.async.cg.shared.global [%0], [%1], 16;\n" :: "r"(s), "l"(g) : "memory");
}

static constexpr int STAGE_BYTES = 32768;                // A 16KB + B 16KB
static constexpr int N_STAGES = 3;
static constexpr int GEMM_SMEM = N_STAGES * STAGE_BYTES; // 96 KB

__global__ __launch_bounds__(128, 2) void gemm_kernel(float* __restrict__ Out)
{
    extern __shared__ char sm[];

    int tid = threadIdx.x;
    int warp = tid >> 5, lane = tid & 31;
    int wm = warp >> 1, wn = warp & 1;          // 2x2 warps of 64x64
    int nt = blockIdx.x, mt = blockIdx.y, b = blockIdx.z;

    const char* Ag = (const char*)(g_Afrag + (size_t)mt * 131072);
    const char* Bg = (const char*)(g_Bfrag + ((size_t)b * 32 + nt) * 131072);

    // stage: A [kk:4][m16:8][lane:32][16B] @0, B [kk:4][n8:16][lane:32][8B] @16384
#define LOAD(s, kt) do {                                                   \
    char* dst = sm + (s) * STAGE_BYTES;                                    \
    const char* ga = Ag + (size_t)(kt) * 16384;                            \
    const char* gb = Bg + (size_t)(kt) * 16384;                            \
    _Pragma("unroll")                                                      \
    for (int i = 0; i < 8; ++i) {                                          \
        cpa16(dst + i * 2048 + tid * 16,         ga + i * 2048 + tid * 16); \
        cpa16(dst + 16384 + i * 2048 + tid * 16, gb + i * 2048 + tid * 16); \
    }                                                                      \
    asm volatile("cp.async.commit_group;\n" ::: "memory");                 \
} while (0)

    float acc[4][8][4];
    #pragma unroll
    for (int im = 0; im < 4; ++im)
        #pragma unroll
        for (int in = 0; in < 8; ++in)
            #pragma unroll
            for (int r = 0; r < 4; ++r) acc[im][in][r] = 0.f;

    LOAD(0, 0);
    LOAD(1, 1);

    for (int kt = 0; kt < 16; ++kt) {
        int s = kt % 3;
        asm volatile("cp.async.wait_group 1;\n" ::: "memory");
        __syncthreads();
        if (kt + 2 < 16)
            LOAD((kt + 2) % 3, kt + 2);
        else
            asm volatile("cp.async.commit_group;\n" ::: "memory");

        const char* stg = sm + s * STAGE_BYTES;

        #pragma unroll
        for (int kk = 0; kk < 4; ++kk) {
            uint32_t afr[4][4];
            uint32_t bfr[8][2];
            #pragma unroll
            for (int im = 0; im < 4; ++im) {
                uint4 v = *(const uint4*)(stg + kk * 4096 + (wm * 4 + im) * 512 + lane * 16);
                afr[im][0] = v.x; afr[im][1] = v.y;
                afr[im][2] = v.z; afr[im][3] = v.w;
            }
            #pragma unroll
            for (int in = 0; in < 8; ++in) {
                uint2 v = *(const uint2*)(stg + 16384 + kk * 4096 + (wn * 8 + in) * 256 + lane * 8);
                bfr[in][0] = v.x; bfr[in][1] = v.y;
            }
            #pragma unroll
            for (int im = 0; im < 4; ++im)
                #pragma unroll
                for (int in = 0; in < 8; ++in)
                    mma_f16(acc[im][in], afr[im], bfr[in]);
        }
    }

    // epilogue
    float* Og = Out + (size_t)b * 2048 * 4096;
    int g = lane >> 2, tg = lane & 3;
    #pragma unroll
    for (int im = 0; im < 4; ++im) {
        #pragma unroll
        for (int in = 0; in < 8; ++in) {
            int row = mt * 128 + wm * 64 + im * 16 + g;
            int col = nt * 128 + wn * 64 + in * 8 + tg * 2;
            float2 v0 = make_float2(acc[im][in][0], acc[im][in][1]);
            float2 v1 = make_float2(acc[im][in][2], acc[im][in][3]);
            *(float2*)&Og[(size_t)row * 4096 + col]       = v0;
            *(float2*)&Og[(size_t)(row + 8) * 4096 + col] = v1;
        }
    }
#undef LOAD
}

// =====================================================================
extern "C" void kernel_launch(void* const* d_in, const int* in_sizes, int n_in,
                              void* d_out, int out_size)
{
    const float* refer = (const float*)d_in[0];
    const float* sup   = (const float*)d_in[1];
    const float* w_off = (const float*)d_in[2];
    const float* b_off = (const float*)d_in[3];
    const float* w_def = (const float*)d_in[4];
    float* out = (float*)d_out;

    conv_wdef_kernel     <<<dim3(8, 4, 34),  256>>>(refer, sup, w_off, w_def);
    offset_combine_kernel<<<dim3(64, 4),     256>>>(b_off);
    sample_kernel        <<<dim3(16, 4, 16), 256>>>(sup);

    cudaFuncSetAttribute(gemm_kernel, cudaFuncAttributeMaxDynamicSharedMemorySize,
                         GEMM_SMEM);
    gemm_kernel<<<dim3(32, 16, 4), 128, GEMM_SMEM>>>(out);
}